// round 2
// baseline (speedup 1.0000x reference)
#include <cuda_runtime.h>
#include <stdint.h>

// MultiLevelHybridHashEncoding — instant-NGP hash-grid encoding.
// B=1e6 points, 16 levels, 2 feats. Levels 0..7 dense, 8..15 hashed (2^19).
//
// R1 -> R2 change: L1tex wavefront-bound (L1=90%). Stage the 3 smallest dense
// tables (levels 0..2, 216.6 KB) in shared memory: scattered LDS is ~10x
// cheaper per gather than scattered LDG in L1TEX. Persistent grid (#SMs CTAs,
// 1024 thr) so the smem fill is paid once per SM. Streaming stores (__stcs)
// for the 128MB output to stop it evicting the hash tables from L2.

#define NLEVELS 16
#define TPB 1024

struct Params {
    const float2* tab[NLEVELS];
};

__device__ __constant__ int c_res[NLEVELS] = {
    16, 20, 25, 32, 40, 50, 64, 80, 101, 128, 161, 203, 256, 322, 406, 512
};

#define L0_N 4096    // 16^3
#define L1_N 8000    // 20^3
#define L2_N 15625   // 25^3
#define SMEM_F2 (L0_N + L1_N + L2_N)          // 27721 float2
#define SMEM_BYTES (SMEM_F2 * 8)              // 221768 B <= 232448 max

extern __shared__ float2 s_tab[];

__global__ void __launch_bounds__(TPB, 1)
hashenc_kernel(const float* __restrict__ x, Params p,
               float2* __restrict__ out, int B)
{
    // ---- cooperative smem fill: levels 0..2, coalesced ----
    {
        const float2* __restrict__ t0 = p.tab[0];
        const float2* __restrict__ t1 = p.tab[1];
        const float2* __restrict__ t2 = p.tab[2];
        for (int i = threadIdx.x; i < L0_N; i += TPB) s_tab[i] = __ldg(t0 + i);
        for (int i = threadIdx.x; i < L1_N; i += TPB) s_tab[L0_N + i] = __ldg(t1 + i);
        for (int i = threadIdx.x; i < L2_N; i += TPB) s_tab[L0_N + L1_N + i] = __ldg(t2 + i);
    }
    __syncthreads();

    const int total = B * NLEVELS;
    const int stride = gridDim.x * TPB;

    for (int tid = blockIdx.x * TPB + threadIdx.x; tid < total; tid += stride) {
        const int b = tid >> 4;
        const int l = tid & 15;

        const int res  = c_res[l];
        const int res2 = res * res;

        // 16 sibling lanes broadcast-load the same point.
        const float px = __ldg(x + 3 * b + 0);
        const float py = __ldg(x + 3 * b + 1);
        const float pz = __ldg(x + 3 * b + 2);

        // xp = (x + 1) * (res/2) - 0.5, exact f32 op order of the reference.
        const float sc = 0.5f * (float)res;
        const float xp = __fadd_rn(__fmul_rn(__fadd_rn(px, 1.0f), sc), -0.5f);
        const float yp = __fadd_rn(__fmul_rn(__fadd_rn(py, 1.0f), sc), -0.5f);
        const float zp = __fadd_rn(__fmul_rn(__fadd_rn(pz, 1.0f), sc), -0.5f);

        const float fx = floorf(xp), fy = floorf(yp), fz = floorf(zp);
        const int ix = (int)fx, iy = (int)fy, iz = (int)fz;
        const float tx = __fsub_rn(xp, fx);
        const float ty = __fsub_rn(yp, fy);
        const float tz = __fsub_rn(zp, fz);
        const float ux = __fsub_rn(1.0f, tx);
        const float uy = __fsub_rn(1.0f, ty);
        const float uz = __fsub_rn(1.0f, tz);

        float a0 = 0.0f, a1 = 0.0f;

        if (l < 3) {
            // ---- dense level resident in shared memory ----
            const float2* __restrict__ t =
                s_tab + (l == 0 ? 0 : (l == 1 ? L0_N : (L0_N + L1_N)));
            #pragma unroll
            for (int ci = 0; ci < 8; ++ci) {
                const int ox = (ci >> 2) & 1, oy = (ci >> 1) & 1, oz = ci & 1;
                const int cx = ix + ox, cy = iy + oy, cz = iz + oz;
                const bool valid = ((unsigned)cx < (unsigned)res) &
                                   ((unsigned)cy < (unsigned)res) &
                                   ((unsigned)cz < (unsigned)res);
                if (valid) {
                    const float w = __fmul_rn(__fmul_rn(ox ? tx : ux, oy ? ty : uy),
                                              oz ? tz : uz);
                    const float2 e = t[cx + cy * res + cz * res2];
                    a0 = fmaf(e.x, w, a0);
                    a1 = fmaf(e.y, w, a1);
                }
            }
        } else {
            // ---- global gather (dense 3..7, hash 8..15) ----
            const bool use_hash = (l >= 8);
            const float2* __restrict__ tab = p.tab[l];
            #pragma unroll
            for (int ci = 0; ci < 8; ++ci) {
                const int ox = (ci >> 2) & 1, oy = (ci >> 1) & 1, oz = ci & 1;
                const int cx = ix + ox, cy = iy + oy, cz = iz + oz;
                const bool valid = ((unsigned)cx < (unsigned)res) &
                                   ((unsigned)cy < (unsigned)res) &
                                   ((unsigned)cz < (unsigned)res);
                if (valid) {
                    const float w = __fmul_rn(__fmul_rn(ox ? tx : ux, oy ? ty : uy),
                                              oz ? tz : uz);
                    unsigned hidx = ((unsigned)cx)
                                  ^ ((unsigned)cy * 2654435761u)
                                  ^ ((unsigned)cz * 805459861u);
                    hidx &= 0x7FFFFu;
                    const unsigned didx = (unsigned)(cx + cy * res + cz * res2);
                    const unsigned idx = use_hash ? hidx : didx;
                    const float2 e = __ldg(&tab[idx]);
                    a0 = fmaf(e.x, w, a0);
                    a1 = fmaf(e.y, w, a1);
                }
            }
        }

        // Streaming store: evict-first, keep hash tables resident in L2.
        __stcs(&out[(size_t)b * NLEVELS + l], make_float2(a0, a1));
    }
}

extern "C" void kernel_launch(void* const* d_in, const int* in_sizes, int n_in,
                              void* d_out, int out_size)
{
    const float* x = (const float*)d_in[0];
    Params p;
    #pragma unroll
    for (int l = 0; l < NLEVELS; ++l) {
        p.tab[l] = (const float2*)d_in[1 + l];
    }
    const int B = in_sizes[0] / 3;

    cudaFuncSetAttribute(hashenc_kernel,
                         cudaFuncAttributeMaxDynamicSharedMemorySize, SMEM_BYTES);

    int sms = 148;
    cudaDeviceGetAttribute(&sms, cudaDevAttrMultiProcessorCount, 0);

    hashenc_kernel<<<sms, TPB, SMEM_BYTES>>>(x, p, (float2*)d_out, B);
}

// round 3
// speedup vs baseline: 1.1227x; 1.1227x over previous
#include <cuda_runtime.h>
#include <stdint.h>

// MultiLevelHybridHashEncoding — instant-NGP hash-grid encoding.
// Levels 0..2 staged in shared memory (216.6 KB), levels 3..15 gathered from L2.
// R2 -> R3: R2 was latency-bound (issue 13%, serial x-load -> gather chain).
// Fixes: software-pipelined x prefetch, batched 8-wide gather issue,
// maskless gathers (idx=0/w=0 for OOB corners, matching the reference).

#define NLEVELS 16
#define TPB 1024

#define L0_N 4096    // 16^3
#define L1_N 8000    // 20^3
#define L2_N 15625   // 25^3
#define SMEM_BYTES ((L0_N + L1_N + L2_N) * 8)   // 221768 B

struct Params {
    const float2* tab[NLEVELS];
};

__device__ __constant__ int c_res[NLEVELS] = {
    16, 20, 25, 32, 40, 50, 64, 80, 101, 128, 161, 203, 256, 322, 406, 512
};

extern __shared__ float2 s_tab[];

__global__ void __launch_bounds__(TPB, 1)
hashenc_kernel(const float* __restrict__ x, Params p,
               float2* __restrict__ out, int B)
{
    // ---- cooperative smem fill: levels 0..2, coalesced ----
    {
        const float2* __restrict__ t0 = p.tab[0];
        const float2* __restrict__ t1 = p.tab[1];
        const float2* __restrict__ t2 = p.tab[2];
        for (int i = threadIdx.x; i < L0_N; i += TPB) s_tab[i] = __ldg(t0 + i);
        for (int i = threadIdx.x; i < L1_N; i += TPB) s_tab[L0_N + i] = __ldg(t1 + i);
        for (int i = threadIdx.x; i < L2_N; i += TPB) s_tab[L0_N + L1_N + i] = __ldg(t2 + i);
    }
    __syncthreads();

    // Loop-invariant per-thread level state (stride is a multiple of 16).
    const int   l        = threadIdx.x & 15;
    const int   res      = c_res[l];
    const int   res2     = res * res;
    const float sc       = 0.5f * (float)res;
    const bool  in_smem  = (l < 3);
    const bool  use_hash = (l >= 8);
    const float2* __restrict__ gtab = p.tab[l];
    const float2* __restrict__ stab =
        s_tab + (l == 0 ? 0 : (l == 1 ? L0_N : (L0_N + L1_N)));

    const int total  = B * NLEVELS;
    const int stride = gridDim.x * TPB;
    int tid = blockIdx.x * TPB + threadIdx.x;
    if (tid >= total) return;

    // Prologue: load first point (16 sibling lanes broadcast the same 12 B).
    float px, py, pz;
    {
        const int b = tid >> 4;
        px = __ldg(x + 3 * b + 0);
        py = __ldg(x + 3 * b + 1);
        pz = __ldg(x + 3 * b + 2);
    }

    while (true) {
        // ---- prefetch next iteration's point (hides x-load latency) ----
        const int tid_n = tid + stride;
        float nx = 0.f, ny = 0.f, nz = 0.f;
        if (tid_n < total) {
            const int bn = tid_n >> 4;
            nx = __ldg(x + 3 * bn + 0);
            ny = __ldg(x + 3 * bn + 1);
            nz = __ldg(x + 3 * bn + 2);
        }

        const int b = tid >> 4;

        // xp = (x + 1) * (res/2) - 0.5, exact f32 op order of the reference.
        const float xp = __fadd_rn(__fmul_rn(__fadd_rn(px, 1.0f), sc), -0.5f);
        const float yp = __fadd_rn(__fmul_rn(__fadd_rn(py, 1.0f), sc), -0.5f);
        const float zp = __fadd_rn(__fmul_rn(__fadd_rn(pz, 1.0f), sc), -0.5f);

        const float fx = floorf(xp), fy = floorf(yp), fz = floorf(zp);
        const int ix = (int)fx, iy = (int)fy, iz = (int)fz;
        const float tx = __fsub_rn(xp, fx);
        const float ty = __fsub_rn(yp, fy);
        const float tz = __fsub_rn(zp, fz);
        const float ux = __fsub_rn(1.0f, tx);
        const float uy = __fsub_rn(1.0f, ty);
        const float uz = __fsub_rn(1.0f, tz);

        // ---- compute all 8 corner weights + indices (maskless: OOB -> idx 0, w 0) ----
        float    w[8];
        unsigned idx[8];
        #pragma unroll
        for (int ci = 0; ci < 8; ++ci) {
            const int ox = (ci >> 2) & 1, oy = (ci >> 1) & 1, oz = ci & 1;
            const int cx = ix + ox, cy = iy + oy, cz = iz + oz;
            const bool valid = ((unsigned)cx < (unsigned)res) &
                               ((unsigned)cy < (unsigned)res) &
                               ((unsigned)cz < (unsigned)res);
            const float ww = __fmul_rn(__fmul_rn(ox ? tx : ux, oy ? ty : uy),
                                       oz ? tz : uz);
            w[ci] = valid ? ww : 0.0f;

            unsigned hidx = ((unsigned)cx)
                          ^ ((unsigned)cy * 2654435761u)
                          ^ ((unsigned)cz * 805459861u);
            hidx &= 0x7FFFFu;
            const unsigned didx = (unsigned)(cx + cy * res + cz * res2);
            const unsigned ii = use_hash ? hidx : didx;
            idx[ci] = valid ? ii : 0u;
        }

        // ---- batched 8-wide gather (max MLP) ----
        float2 e[8];
        if (in_smem) {
            #pragma unroll
            for (int ci = 0; ci < 8; ++ci) e[ci] = stab[idx[ci]];
        } else {
            #pragma unroll
            for (int ci = 0; ci < 8; ++ci) e[ci] = __ldg(&gtab[idx[ci]]);
        }

        float a0 = 0.0f, a1 = 0.0f;
        #pragma unroll
        for (int ci = 0; ci < 8; ++ci) {
            a0 = fmaf(e[ci].x, w[ci], a0);
            a1 = fmaf(e[ci].y, w[ci], a1);
        }

        // Streaming store: evict-first, keep hash tables resident in L2.
        __stcs(&out[(size_t)b * NLEVELS + l], make_float2(a0, a1));

        if (tid_n >= total) break;
        tid = tid_n;
        px = nx; py = ny; pz = nz;
    }
}

extern "C" void kernel_launch(void* const* d_in, const int* in_sizes, int n_in,
                              void* d_out, int out_size)
{
    const float* x = (const float*)d_in[0];
    Params p;
    #pragma unroll
    for (int l = 0; l < NLEVELS; ++l) {
        p.tab[l] = (const float2*)d_in[1 + l];
    }
    const int B = in_sizes[0] / 3;

    cudaFuncSetAttribute(hashenc_kernel,
                         cudaFuncAttributeMaxDynamicSharedMemorySize, SMEM_BYTES);

    int sms = 148;
    cudaDeviceGetAttribute(&sms, cudaDevAttrMultiProcessorCount, 0);

    hashenc_kernel<<<sms, TPB, SMEM_BYTES>>>(x, p, (float2*)d_out, B);
}

// round 4
// speedup vs baseline: 1.9865x; 1.7694x over previous
#include <cuda_runtime.h>
#include <stdint.h>

// MultiLevelHybridHashEncoding — instant-NGP hash-grid encoding.
// R3 -> R4: R3 was occupancy-starved (221KB smem -> 32 warps/SM, issue 11%).
// Re-trade: stage only levels 0..1 (96.8 KB) so 2 CTAs x 768 thr = 48 warps/SM
// fit both smem (193.5/228 KB) and regfile (42 regs). Keep batched 8-wide
// gathers, x-prefetch pipeline, maskless OOB handling, streaming stores.

#define NLEVELS 16
#define TPB 768

#define L0_N 4096    // 16^3
#define L1_N 8000    // 20^3
#define SMEM_BYTES ((L0_N + L1_N) * 8)   // 96768 B per CTA

struct Params {
    const float2* tab[NLEVELS];
};

__device__ __constant__ int c_res[NLEVELS] = {
    16, 20, 25, 32, 40, 50, 64, 80, 101, 128, 161, 203, 256, 322, 406, 512
};

extern __shared__ float2 s_tab[];

__global__ void __launch_bounds__(TPB, 2)
hashenc_kernel(const float* __restrict__ x, Params p,
               float2* __restrict__ out, int B)
{
    // ---- cooperative smem fill: levels 0..1, coalesced ----
    {
        const float2* __restrict__ t0 = p.tab[0];
        const float2* __restrict__ t1 = p.tab[1];
        for (int i = threadIdx.x; i < L0_N; i += TPB) s_tab[i] = __ldg(t0 + i);
        for (int i = threadIdx.x; i < L1_N; i += TPB) s_tab[L0_N + i] = __ldg(t1 + i);
    }
    __syncthreads();

    // Loop-invariant per-thread level state (stride is a multiple of 16).
    const int   l        = threadIdx.x & 15;
    const int   res      = c_res[l];
    const int   res2     = res * res;
    const float sc       = 0.5f * (float)res;
    const bool  in_smem  = (l < 2);
    const bool  use_hash = (l >= 8);
    const float2* __restrict__ gtab = p.tab[l];
    const float2* __restrict__ stab = s_tab + (l == 0 ? 0 : L0_N);

    const int total  = B * NLEVELS;
    const int stride = gridDim.x * TPB;
    int tid = blockIdx.x * TPB + threadIdx.x;
    if (tid >= total) return;

    // Prologue: load first point (16 sibling lanes broadcast the same 12 B).
    float px, py, pz;
    {
        const int b = tid >> 4;
        px = __ldg(x + 3 * b + 0);
        py = __ldg(x + 3 * b + 1);
        pz = __ldg(x + 3 * b + 2);
    }

    while (true) {
        // ---- prefetch next iteration's point (hides x-load latency) ----
        const int tid_n = tid + stride;
        float nx = 0.f, ny = 0.f, nz = 0.f;
        if (tid_n < total) {
            const int bn = tid_n >> 4;
            nx = __ldg(x + 3 * bn + 0);
            ny = __ldg(x + 3 * bn + 1);
            nz = __ldg(x + 3 * bn + 2);
        }

        const int b = tid >> 4;

        // xp = (x + 1) * (res/2) - 0.5, exact f32 op order of the reference.
        const float xp = __fadd_rn(__fmul_rn(__fadd_rn(px, 1.0f), sc), -0.5f);
        const float yp = __fadd_rn(__fmul_rn(__fadd_rn(py, 1.0f), sc), -0.5f);
        const float zp = __fadd_rn(__fmul_rn(__fadd_rn(pz, 1.0f), sc), -0.5f);

        const float fx = floorf(xp), fy = floorf(yp), fz = floorf(zp);
        const int ix = (int)fx, iy = (int)fy, iz = (int)fz;
        const float tx = __fsub_rn(xp, fx);
        const float ty = __fsub_rn(yp, fy);
        const float tz = __fsub_rn(zp, fz);
        const float ux = __fsub_rn(1.0f, tx);
        const float uy = __fsub_rn(1.0f, ty);
        const float uz = __fsub_rn(1.0f, tz);

        // ---- all 8 corner weights + indices (maskless: OOB -> idx 0, w 0) ----
        float    w[8];
        unsigned idx[8];
        #pragma unroll
        for (int ci = 0; ci < 8; ++ci) {
            const int ox = (ci >> 2) & 1, oy = (ci >> 1) & 1, oz = ci & 1;
            const int cx = ix + ox, cy = iy + oy, cz = iz + oz;
            const bool valid = ((unsigned)cx < (unsigned)res) &
                               ((unsigned)cy < (unsigned)res) &
                               ((unsigned)cz < (unsigned)res);
            const float ww = __fmul_rn(__fmul_rn(ox ? tx : ux, oy ? ty : uy),
                                       oz ? tz : uz);
            w[ci] = valid ? ww : 0.0f;

            unsigned hidx = ((unsigned)cx)
                          ^ ((unsigned)cy * 2654435761u)
                          ^ ((unsigned)cz * 805459861u);
            hidx &= 0x7FFFFu;
            const unsigned didx = (unsigned)(cx + cy * res + cz * res2);
            const unsigned ii = use_hash ? hidx : didx;
            idx[ci] = valid ? ii : 0u;
        }

        // ---- batched 8-wide gather (max MLP) ----
        float2 e[8];
        if (in_smem) {
            #pragma unroll
            for (int ci = 0; ci < 8; ++ci) e[ci] = stab[idx[ci]];
        } else {
            #pragma unroll
            for (int ci = 0; ci < 8; ++ci) e[ci] = __ldg(&gtab[idx[ci]]);
        }

        float a0 = 0.0f, a1 = 0.0f;
        #pragma unroll
        for (int ci = 0; ci < 8; ++ci) {
            a0 = fmaf(e[ci].x, w[ci], a0);
            a1 = fmaf(e[ci].y, w[ci], a1);
        }

        // Streaming store: evict-first, keep hash tables resident in L2.
        __stcs(&out[(size_t)b * NLEVELS + l], make_float2(a0, a1));

        if (tid_n >= total) break;
        tid = tid_n;
        px = nx; py = ny; pz = nz;
    }
}

extern "C" void kernel_launch(void* const* d_in, const int* in_sizes, int n_in,
                              void* d_out, int out_size)
{
    const float* x = (const float*)d_in[0];
    Params p;
    #pragma unroll
    for (int l = 0; l < NLEVELS; ++l) {
        p.tab[l] = (const float2*)d_in[1 + l];
    }
    const int B = in_sizes[0] / 3;

    cudaFuncSetAttribute(hashenc_kernel,
                         cudaFuncAttributeMaxDynamicSharedMemorySize, SMEM_BYTES);

    int sms = 148;
    cudaDeviceGetAttribute(&sms, cudaDevAttrMultiProcessorCount, 0);

    hashenc_kernel<<<2 * sms, TPB, SMEM_BYTES>>>(x, p, (float2*)d_out, B);
}

// round 5
// speedup vs baseline: 3.1684x; 1.5949x over previous
#include <cuda_runtime.h>
#include <stdint.h>

// MultiLevelHybridHashEncoding — instant-NGP hash-grid encoding.
// R4 -> R5: cut L1TEX line-wavefronts by pairing the two x-adjacent corners
// onto adjacent lanes (dense: idx+1 same 128B line 94%; hash: cx even ->
// idx^1 same line, 50%). 2 lanes per (point,level): lane parity = ox corner,
// each lane gathers its 4 (oy,oz) corners; pair-reduce via shfl_xor(1).
// Levels 0..1 stay staged in shared memory (96.8 KB, 2 CTAs x 768 thr/SM).

#define NLEVELS 16
#define TPB 768

#define L0_N 4096    // 16^3
#define L1_N 8000    // 20^3
#define SMEM_BYTES ((L0_N + L1_N) * 8)   // 96768 B per CTA

struct Params {
    const float2* tab[NLEVELS];
};

__device__ __constant__ int c_res[NLEVELS] = {
    16, 20, 25, 32, 40, 50, 64, 80, 101, 128, 161, 203, 256, 322, 406, 512
};

extern __shared__ float2 s_tab[];

__global__ void __launch_bounds__(TPB, 2)
hashenc_kernel(const float* __restrict__ x, Params p,
               float2* __restrict__ out, int B)
{
    // ---- cooperative smem fill: levels 0..1, coalesced ----
    {
        const float2* __restrict__ t0 = p.tab[0];
        const float2* __restrict__ t1 = p.tab[1];
        for (int i = threadIdx.x; i < L0_N; i += TPB) s_tab[i] = __ldg(t0 + i);
        for (int i = threadIdx.x; i < L1_N; i += TPB) s_tab[L0_N + i] = __ldg(t1 + i);
    }
    __syncthreads();

    // Thread = (point, level, x-half). 32 consecutive threads = 1 point.
    // Loop-invariant state (stride is a multiple of 32).
    const int   ox       = threadIdx.x & 1;        // x-corner this lane owns
    const int   l        = (threadIdx.x >> 1) & 15;
    const int   res      = c_res[l];
    const int   res2     = res * res;
    const float sc       = 0.5f * (float)res;
    const bool  in_smem  = (l < 2);
    const bool  use_hash = (l >= 8);
    const float2* __restrict__ gtab = p.tab[l];
    const float2* __restrict__ stab = s_tab + (l == 0 ? 0 : L0_N);

    const int total  = B * NLEVELS * 2;             // (point, level, half) items
    const int stride = gridDim.x * TPB;
    int tid = blockIdx.x * TPB + threadIdx.x;
    if (tid >= total) return;

    // Prologue: load first point (all 32 lanes broadcast the same 12 B).
    float px, py, pz;
    {
        const int b = tid >> 5;
        px = __ldg(x + 3 * b + 0);
        py = __ldg(x + 3 * b + 1);
        pz = __ldg(x + 3 * b + 2);
    }

    while (true) {
        // ---- prefetch next iteration's point ----
        const int tid_n = tid + stride;
        float nx = 0.f, ny = 0.f, nz = 0.f;
        if (tid_n < total) {
            const int bn = tid_n >> 5;
            nx = __ldg(x + 3 * bn + 0);
            ny = __ldg(x + 3 * bn + 1);
            nz = __ldg(x + 3 * bn + 2);
        }

        const int b = tid >> 5;

        // xp = (x + 1) * (res/2) - 0.5, exact f32 op order of the reference.
        const float xp = __fadd_rn(__fmul_rn(__fadd_rn(px, 1.0f), sc), -0.5f);
        const float yp = __fadd_rn(__fmul_rn(__fadd_rn(py, 1.0f), sc), -0.5f);
        const float zp = __fadd_rn(__fmul_rn(__fadd_rn(pz, 1.0f), sc), -0.5f);

        const float fx = floorf(xp), fy = floorf(yp), fz = floorf(zp);
        const int ix = (int)fx, iy = (int)fy, iz = (int)fz;
        const float tx = __fsub_rn(xp, fx);
        const float ty = __fsub_rn(yp, fy);
        const float tz = __fsub_rn(zp, fz);
        const float ux = __fsub_rn(1.0f, tx);
        const float uy = __fsub_rn(1.0f, ty);
        const float uz = __fsub_rn(1.0f, tz);

        // This lane's x-corner (shared by its 4 corners).
        const int   cx   = ix + ox;
        const float wx   = ox ? tx : ux;
        const bool  vx   = ((unsigned)cx < (unsigned)res);
        const unsigned hx = (unsigned)cx;            // cx * PRIME0(=1)
        const int   dx   = cx;

        // ---- 4 corners (oy,oz); paired lanes (ox=0/1) coalesce in L1TEX ----
        float    w[4];
        unsigned idx[4];
        #pragma unroll
        for (int cc = 0; cc < 4; ++cc) {
            const int oy = (cc >> 1) & 1, oz = cc & 1;
            const int cy = iy + oy, cz = iz + oz;
            const bool valid = vx &
                               ((unsigned)cy < (unsigned)res) &
                               ((unsigned)cz < (unsigned)res);
            const float ww = __fmul_rn(__fmul_rn(wx, oy ? ty : uy), oz ? tz : uz);
            w[cc] = valid ? ww : 0.0f;

            unsigned hidx = hx
                          ^ ((unsigned)cy * 2654435761u)
                          ^ ((unsigned)cz * 805459861u);
            hidx &= 0x7FFFFu;
            const unsigned didx = (unsigned)(dx + cy * res + cz * res2);
            const unsigned ii = use_hash ? hidx : didx;
            idx[cc] = valid ? ii : 0u;
        }

        // ---- batched 4-wide gather ----
        float2 e[4];
        if (in_smem) {
            #pragma unroll
            for (int cc = 0; cc < 4; ++cc) e[cc] = stab[idx[cc]];
        } else {
            #pragma unroll
            for (int cc = 0; cc < 4; ++cc) e[cc] = __ldg(&gtab[idx[cc]]);
        }

        float a0 = 0.0f, a1 = 0.0f;
        #pragma unroll
        for (int cc = 0; cc < 4; ++cc) {
            a0 = fmaf(e[cc].x, w[cc], a0);
            a1 = fmaf(e[cc].y, w[cc], a1);
        }

        // Pair reduction: even lane gets (its 4 corners) + (odd lane's 4).
        a0 += __shfl_xor_sync(0xffffffffu, a0, 1);
        a1 += __shfl_xor_sync(0xffffffffu, a1, 1);

        if (ox == 0) {
            // 16 even lanes store 128 contiguous bytes per warp.
            __stcs(&out[(size_t)b * NLEVELS + l], make_float2(a0, a1));
        }

        if (tid_n >= total) break;
        tid = tid_n;
        px = nx; py = ny; pz = nz;
    }
}

extern "C" void kernel_launch(void* const* d_in, const int* in_sizes, int n_in,
                              void* d_out, int out_size)
{
    const float* x = (const float*)d_in[0];
    Params p;
    #pragma unroll
    for (int l = 0; l < NLEVELS; ++l) {
        p.tab[l] = (const float2*)d_in[1 + l];
    }
    const int B = in_sizes[0] / 3;

    cudaFuncSetAttribute(hashenc_kernel,
                         cudaFuncAttributeMaxDynamicSharedMemorySize, SMEM_BYTES);

    int sms = 148;
    cudaDeviceGetAttribute(&sms, cudaDevAttrMultiProcessorCount, 0);

    hashenc_kernel<<<2 * sms, TPB, SMEM_BYTES>>>(x, p, (float2*)d_out, B);
}